// round 1
// baseline (speedup 1.0000x reference)
#include <cuda_runtime.h>
#include <cuda_bf16.h>

// Radix-select top-k mask. Keys = fp32 bit pattern of |x| (monotonic for
// non-negative floats). 3 passes of 10 bits (keys < 2^30 since |x| < 2).
// Exact stable-sort tie handling at the threshold via index-ordered fixup.

#define NBINS 1024
#define MAX_EQ 65536

struct SelState {
    unsigned int prefix;  // accumulated key prefix; after pass3 == threshold key T
    unsigned int rank;    // remaining rank within current prefix group; after pass3 == z
};

__device__ unsigned int g_hist[NBINS];
__device__ SelState     g_state;
__device__ unsigned int g_eq_idx[MAX_EQ];
__device__ unsigned int g_eq_cnt;

__global__ void reset_kernel(unsigned int j) {
    int t = threadIdx.x;
    if (t < NBINS) g_hist[t] = 0;
    if (t == 0) {
        g_state.prefix = 0;
        g_state.rank = j;
        g_eq_cnt = 0;
    }
}

__device__ __forceinline__ unsigned int abskey(float v) {
    return __float_as_uint(v) & 0x7FFFFFFFu;
}

__global__ void hist_kernel(const float4* __restrict__ in, int n4, int shift) {
    __shared__ unsigned int sh[NBINS];
    for (int i = threadIdx.x; i < NBINS; i += blockDim.x) sh[i] = 0;
    __syncthreads();
    const unsigned int prefix = g_state.prefix;
    const int hishift = shift + 10;  // bits above this pass must match prefix
    int stride = gridDim.x * blockDim.x;
    for (int i = blockIdx.x * blockDim.x + threadIdx.x; i < n4; i += stride) {
        float4 v = in[i];
        unsigned int k;
        k = abskey(v.x); if (((k ^ prefix) >> hishift) == 0) atomicAdd(&sh[(k >> shift) & (NBINS - 1)], 1u);
        k = abskey(v.y); if (((k ^ prefix) >> hishift) == 0) atomicAdd(&sh[(k >> shift) & (NBINS - 1)], 1u);
        k = abskey(v.z); if (((k ^ prefix) >> hishift) == 0) atomicAdd(&sh[(k >> shift) & (NBINS - 1)], 1u);
        k = abskey(v.w); if (((k ^ prefix) >> hishift) == 0) atomicAdd(&sh[(k >> shift) & (NBINS - 1)], 1u);
    }
    __syncthreads();
    for (int i = threadIdx.x; i < NBINS; i += blockDim.x)
        if (sh[i]) atomicAdd(&g_hist[i], sh[i]);
}

// One block of NBINS threads: inclusive scan, pick the bin containing rank,
// refine prefix/rank, and zero the histogram for the next pass.
__global__ void scan_kernel(int shift) {
    __shared__ unsigned int s[NBINS];
    int t = threadIdx.x;
    unsigned int rank = g_state.rank;   // read by all threads BEFORE any write
    unsigned int v = g_hist[t];
    g_hist[t] = 0;
    s[t] = v;
    __syncthreads();
    // Hillis-Steele inclusive scan over NBINS
    for (int off = 1; off < NBINS; off <<= 1) {
        unsigned int x = (t >= off) ? s[t - off] : 0u;
        __syncthreads();
        s[t] += x;
        __syncthreads();
    }
    unsigned int incl = s[t];
    unsigned int before = incl - v;
    if (before <= rank && rank < incl) {
        g_state.prefix |= ((unsigned int)t) << shift;
        g_state.rank = rank - before;
    }
}

__global__ void mask_kernel(const float4* __restrict__ in, float4* __restrict__ out, int n4) {
    const unsigned int T = g_state.prefix;
    int stride = gridDim.x * blockDim.x;
    for (int i = blockIdx.x * blockDim.x + threadIdx.x; i < n4; i += stride) {
        float4 v = in[i];
        float4 r;
        unsigned int base = ((unsigned int)i) << 2;
        unsigned int k;

        k = abskey(v.x);
        r.x = (k >= T) ? 1.0f : 0.0f;
        if (k == T) { unsigned int p = atomicAdd(&g_eq_cnt, 1u); if (p < MAX_EQ) g_eq_idx[p] = base + 0; }
        k = abskey(v.y);
        r.y = (k >= T) ? 1.0f : 0.0f;
        if (k == T) { unsigned int p = atomicAdd(&g_eq_cnt, 1u); if (p < MAX_EQ) g_eq_idx[p] = base + 1; }
        k = abskey(v.z);
        r.z = (k >= T) ? 1.0f : 0.0f;
        if (k == T) { unsigned int p = atomicAdd(&g_eq_cnt, 1u); if (p < MAX_EQ) g_eq_idx[p] = base + 2; }
        k = abskey(v.w);
        r.w = (k >= T) ? 1.0f : 0.0f;
        if (k == T) { unsigned int p = atomicAdd(&g_eq_cnt, 1u); if (p < MAX_EQ) g_eq_idx[p] = base + 3; }

        out[i] = r;
    }
}

// Among the elements equal to T, the first z in ascending flat-index order
// belong to the "dropped" ranks (stable argsort tie-break) -> set to 0.
__global__ void fixup_kernel(float* __restrict__ out) {
    unsigned int m = g_eq_cnt;
    if (m > MAX_EQ) m = MAX_EQ;
    unsigned int z = g_state.rank;
    unsigned int t = blockIdx.x * blockDim.x + threadIdx.x;
    if (t >= m) return;
    unsigned int idx = g_eq_idx[t];
    unsigned int c = 0;
    for (unsigned int s = 0; s < m; s++)
        c += (g_eq_idx[s] < idx) ? 1u : 0u;
    if (c < z) out[idx] = 0.0f;
}

extern "C" void kernel_launch(void* const* d_in, const int* in_sizes, int n_in,
                              void* d_out, int out_size) {
    const float* A = (const float*)d_in[0];
    const float* B = (const float*)d_in[1];
    float* out = (float*)d_out;

    int n = in_sizes[0];                 // 16777216
    int n4 = n / 4;
    // Mirrors python: j = int((1.0 - 0.1) * n)
    unsigned int j = (unsigned int)((1.0 - 0.1) * (double)n);

    const int HBLK = 2048, HTHR = 256;

    for (int m = 0; m < 2; m++) {
        const float* src = (m == 0) ? A : B;
        float* dst = out + (size_t)m * (size_t)n;

        reset_kernel<<<1, NBINS>>>(j);
        hist_kernel<<<HBLK, HTHR>>>((const float4*)src, n4, 20);
        scan_kernel<<<1, NBINS>>>(20);
        hist_kernel<<<HBLK, HTHR>>>((const float4*)src, n4, 10);
        scan_kernel<<<1, NBINS>>>(10);
        hist_kernel<<<HBLK, HTHR>>>((const float4*)src, n4, 0);
        scan_kernel<<<1, NBINS>>>(0);
        mask_kernel<<<HBLK, HTHR>>>((const float4*)src, (float4*)dst, n4);
        fixup_kernel<<<MAX_EQ / 256, 256>>>(dst);
    }
}